// round 13
// baseline (speedup 1.0000x reference)
#include <cuda_runtime.h>
#include <cuda_fp16.h>
#include <cstdint>
#include <math.h>

#define NXC 49152
#define NYC 50000
#define NT_Y 391
#define NY_PAD (NT_Y*128)          // 50048
#define CDIM 128
#define KTOP 10
#define DEPTH 12
#define NCAND 96                   // 2 splits * 4 class-threads * 12
#define NXK (NXC*KTOP)
#define INV_TAU 20.0f

#define MTILES (NXC/64)            // 768
#define SPLIT_T 196                // split0: [0,196), split1: [196,391)

// gemm smem: A 16KB @0, B0 32KB @16384, B1 32KB @49152
#define SM_B0 16384
#define SM_B1 49152
#define SM_TOTAL 81920

#define NPACK_X (MTILES*1024)
#define NPACK_Y (NT_Y*2048)

// ---------------- device scratch ----------------
__device__ float g_x32[NXC*CDIM];      // normalized x, row-major (exact fp32)
__device__ float g_y32[NY_PAD*CDIM];   // normalized y, row-major, zero-padded
__device__ uint4 g_xA[NPACK_X];        // fp16 A fragment images: 16KB per 64-row tile
__device__ uint4 g_yB[NPACK_Y];        // fp16 B fragment images: 32KB per 128-col tile
__device__ int   g_candI[NXC*NCAND];   // candidate cols per row

// ---------------- helpers ----------------
__device__ __forceinline__ unsigned h2(float a, float b) {
    __half2 h = __floats2half2_rn(a, b);   // .x = low half
    return *(unsigned*)&h;
}
__device__ __forceinline__ void mma_f16(float (&c)[4], const uint4& a, unsigned b0, unsigned b1) {
    asm volatile(
        "mma.sync.aligned.m16n8k16.row.col.f32.f16.f16.f32 "
        "{%0,%1,%2,%3}, {%4,%5,%6,%7}, {%8,%9}, {%0,%1,%2,%3};"
        : "+f"(c[0]), "+f"(c[1]), "+f"(c[2]), "+f"(c[3])
        : "r"(a.x), "r"(a.y), "r"(a.z), "r"(a.w), "r"(b0), "r"(b1));
}
__device__ __forceinline__ void insert12(float (&tv)[12], int (&ti)[12], float v, int j) {
    tv[11] = v; ti[11] = j;
#pragma unroll
    for (int s = 11; s > 0; --s) {
        bool sw = (tv[s] > tv[s-1]) || (tv[s] == tv[s-1] && ti[s] < ti[s-1]);
        if (sw) {
            float fv = tv[s]; tv[s] = tv[s-1]; tv[s-1] = fv;
            int   fi = ti[s]; ti[s] = ti[s-1]; ti[s-1] = fi;
        }
    }
}
__device__ __forceinline__ void insert10(float (&tv)[10], int (&ti)[10], float v, int j) {
    tv[9] = v; ti[9] = j;
#pragma unroll
    for (int s = 9; s > 0; --s) {
        bool sw = (tv[s] > tv[s-1]) || (tv[s] == tv[s-1] && ti[s] < ti[s-1]);
        if (sw) {
            float fv = tv[s]; tv[s] = tv[s-1]; tv[s-1] = fv;
            int   fi = ti[s]; ti[s] = ti[s-1]; ti[s-1] = fi;
        }
    }
}

// ---------------- normalize (EXACT same arithmetic as the passing chain) ----------------
__global__ void norm_x_kernel(const float* __restrict__ in) {
    int warp = (blockIdx.x * blockDim.x + threadIdx.x) >> 5;
    int lane = threadIdx.x & 31;
    if (warp >= NXC) return;
    float4 v = *(const float4*)&in[warp * CDIM + lane * 4];
    float ss = v.x*v.x + v.y*v.y + v.z*v.z + v.w*v.w;
#pragma unroll
    for (int o = 16; o > 0; o >>= 1) ss += __shfl_xor_sync(0xffffffffu, ss, o);
    float inv = 1.0f / fmaxf(sqrtf(ss), 1e-12f);
    *(float4*)&g_x32[warp * CDIM + lane * 4] = make_float4(v.x*inv, v.y*inv, v.z*inv, v.w*inv);
}
__global__ void norm_y_kernel(const float* __restrict__ in) {
    int warp = (blockIdx.x * blockDim.x + threadIdx.x) >> 5;
    int lane = threadIdx.x & 31;
    if (warp >= NY_PAD) return;
    if (warp >= NYC) {
        *(float4*)&g_y32[warp * CDIM + lane * 4] = make_float4(0.f, 0.f, 0.f, 0.f);
        return;
    }
    float4 v = *(const float4*)&in[warp * CDIM + lane * 4];
    float ss = v.x*v.x + v.y*v.y + v.z*v.z + v.w*v.w;
#pragma unroll
    for (int o = 16; o > 0; o >>= 1) ss += __shfl_xor_sync(0xffffffffu, ss, o);
    float inv = 1.0f / fmaxf(sqrtf(ss), 1e-12f);
    *(float4*)&g_y32[warp * CDIM + lane * 4] = make_float4(v.x*inv, v.y*inv, v.z*inv, v.w*inv);
}

// ---------------- fused fp16 fragment packing (single launch -> gemm is launch #4) ----
// A image per 64-row mtile: uint4 i = mt*1024 + (f*8 + k16)*32 + lane
//   lane=i&31, k16=(i>>5)&7, f=(i>>8)&3, mt=i>>10
//   g=lane>>2, t=lane&3; r=mt*64+f*16+g; k0=k16*16+t*2
// B image per 128-col ytile: uint4 j = yt*2048 + (k16*8 + p)*32 + lane
//   lane=j&31, p=(j>>5)&7, k16=(j>>8)&7, yt=j>>11
//   n_e=yt*128+p*16+g (b0,b1), n_o=n_e+8 (b0,b1); k0=k16*16+t*2
__global__ void pack_xy_frag() {
    int i = blockIdx.x * blockDim.x + threadIdx.x;
    if (i < NPACK_X) {
        int lane = i & 31;
        int k16  = (i >> 5) & 7;
        int f    = (i >> 8) & 3;
        int mt   = i >> 10;
        int g = lane >> 2, t = lane & 3;
        int r = mt * 64 + f * 16 + g;
        int k0 = k16 * 16 + t * 2;
        uint4 a;
        a.x = h2(g_x32[r * CDIM + k0],           g_x32[r * CDIM + k0 + 1]);
        a.y = h2(g_x32[(r + 8) * CDIM + k0],     g_x32[(r + 8) * CDIM + k0 + 1]);
        a.z = h2(g_x32[r * CDIM + k0 + 8],       g_x32[r * CDIM + k0 + 9]);
        a.w = h2(g_x32[(r + 8) * CDIM + k0 + 8], g_x32[(r + 8) * CDIM + k0 + 9]);
        g_xA[i] = a;
        return;
    }
    int j = i - NPACK_X;
    if (j >= NPACK_Y) return;
    int lane = j & 31, p = (j >> 5) & 7, k16 = (j >> 8) & 7, yt = j >> 11;
    int g = lane >> 2, t = lane & 3;
    int ce = yt * 128 + p * 16 + g;        // even n-frag column
    int co = ce + 8;                       // odd n-frag column
    int k0 = k16 * 16 + t * 2;
    uint4 b;
    b.x = h2(g_y32[ce * CDIM + k0],     g_y32[ce * CDIM + k0 + 1]);
    b.y = h2(g_y32[ce * CDIM + k0 + 8], g_y32[ce * CDIM + k0 + 9]);
    b.z = h2(g_y32[co * CDIM + k0],     g_y32[co * CDIM + k0 + 1]);
    b.w = h2(g_y32[co * CDIM + k0 + 8], g_y32[co * CDIM + k0 + 9]);
    g_yB[j] = b;
}

// ---------------- cp.async helpers (128 threads) ----------------
__device__ __forceinline__ void cp_B(char* dst_sm, int yt, int tid) {
    const char* src = (const char*)(g_yB + (size_t)yt * 2048);
#pragma unroll
    for (int i = 0; i < 16; i++) {
        int off = (tid + 128 * i) * 16;
        unsigned s = (unsigned)__cvta_generic_to_shared(dst_sm + off);
        asm volatile("cp.async.cg.shared.global [%0], [%1], 16;" :: "r"(s), "l"(src + off));
    }
    asm volatile("cp.async.commit_group;" ::: "memory");
}
__device__ __forceinline__ void cp_A(char* dst_sm, int mt, int tid) {
    const char* src = (const char*)(g_xA + (size_t)mt * 1024);
#pragma unroll
    for (int i = 0; i < 8; i++) {
        int off = (tid + 128 * i) * 16;
        unsigned s = (unsigned)__cvta_generic_to_shared(dst_sm + off);
        asm volatile("cp.async.cg.shared.global [%0], [%1], 16;" :: "r"(s), "l"(src + off));
    }
    asm volatile("cp.async.commit_group;" ::: "memory");
}

// ---------------- fp16 mma GEMM + in-register streaming top-12 ----------------
__global__ __launch_bounds__(128, 2) void gemm_topk_kernel() {
    extern __shared__ char sm[];
    const int tid  = threadIdx.x;
    const int w    = tid >> 5;
    const int lane = tid & 31;
    const int g    = lane >> 2;
    const int t4   = lane & 3;
    const int mtile = blockIdx.x;
    const int split = blockIdx.y;
    const int t_lo = split * SPLIT_T;
    const int t_hi = split ? NT_Y : SPLIT_T;

    cp_A(sm, mtile, tid);
    cp_B(sm + SM_B0, t_lo, tid);

    const uint4* AsW = (const uint4*)sm + w * 8 * 32;   // this warp's m-frag, 8 k16 slabs

    float tvA[12], tvB[12]; int tiA[12], tiB[12];
#pragma unroll
    for (int q = 0; q < 12; q++) {
        tvA[q] = tvB[q] = -__int_as_float(0x7f800000);
        tiA[q] = tiB[q] = 0x7fffffff;
    }

    for (int t = t_lo; t < t_hi; t++) {
        if (t + 1 < t_hi) {
            cp_B(sm + (((t + 1) & 1) ? SM_B1 : SM_B0), t + 1, tid);
            asm volatile("cp.async.wait_group 1;" ::: "memory");
        } else {
            asm volatile("cp.async.wait_group 0;" ::: "memory");
        }
        __syncthreads();

        const uint4* Bs = (const uint4*)(sm + ((t & 1) ? SM_B1 : SM_B0));

        float acc[16][4];
#pragma unroll
        for (int nf = 0; nf < 16; nf++)
#pragma unroll
            for (int p = 0; p < 4; p++) acc[nf][p] = 0.0f;

#pragma unroll
        for (int k16 = 0; k16 < 8; k16++) {
            uint4 a = AsW[k16 * 32 + lane];
            const uint4* Bk = Bs + k16 * 8 * 32;
#pragma unroll
            for (int p = 0; p < 8; p++) {
                uint4 bb = Bk[p * 32 + lane];
                mma_f16(acc[2*p],     a, bb.x, bb.y);
                mma_f16(acc[2*p + 1], a, bb.z, bb.w);
            }
        }

        // scan accumulators: this thread owns rows (g, g+8), cols nf*8 + t4*2 + {0,1}
        int n0 = t * 128 + t4 * 2;
#pragma unroll
        for (int nf = 0; nf < 16; nf++) {
            int j0 = n0 + nf * 8;
            float v0 = acc[nf][0], v1 = acc[nf][1], v2 = acc[nf][2], v3 = acc[nf][3];
            if (v0 > tvA[11] && j0 < NYC)     insert12(tvA, tiA, v0, j0);
            if (v1 > tvA[11] && j0 + 1 < NYC) insert12(tvA, tiA, v1, j0 + 1);
            if (v2 > tvB[11] && j0 < NYC)     insert12(tvB, tiB, v2, j0);
            if (v3 > tvB[11] && j0 + 1 < NYC) insert12(tvB, tiB, v3, j0 + 1);
        }
        __syncthreads();   // all warps done with this B buffer before next-iter cp overwrites it
    }

    int mA = mtile * 64 + w * 16 + g;
    int mB = mA + 8;
    int base = split * 48 + t4 * 12;
#pragma unroll
    for (int q = 0; q < 12; q++) {
        g_candI[mA * NCAND + base + q] = tiA[q];
        g_candI[mB * NCAND + base + q] = tiB[q];
    }
}

// ---------------- exact fp32 rescore (bitwise-identical chain) + softmax + COO ----------------
__global__ __launch_bounds__(128) void rescore_kernel(float* __restrict__ out) {
    extern __shared__ float rs[];
    float* xrow  = rs;                        // 128
    float* yrows = rs + 128;                  // 96 * 129 (pitch 129 -> conflict-free)
    float* vals  = yrows + 96 * 129;          // 96
    int*   cols  = (int*)(vals + 96);         // 96

    const int m = blockIdx.x;
    const int tid = threadIdx.x;

    if (tid < 128) xrow[tid] = g_x32[m * CDIM + tid];
    if (tid < 96)  cols[tid] = g_candI[m * NCAND + tid];
    __syncthreads();

    for (int i = tid; i < 96 * 32; i += 128) {
        int c = i >> 5, p = i & 31;
        float4 v = *(const float4*)&g_y32[(size_t)cols[c] * CDIM + p * 4];
        float* dst = &yrows[c * 129 + p * 4];
        dst[0] = v.x; dst[1] = v.y; dst[2] = v.z; dst[3] = v.w;
    }
    __syncthreads();

    if (tid < 96) {
        float s = 0.0f;
        const float* yr = &yrows[tid * 129];
#pragma unroll 16
        for (int k = 0; k < 128; k++) s = fmaf(xrow[k], yr[k], s);
        vals[tid] = s;
    }
    __syncthreads();

    if (tid == 0) {
        float tv[10]; int tix[10];
#pragma unroll
        for (int q = 0; q < 10; q++) { tv[q] = -__int_as_float(0x7f800000); tix[q] = 0x7fffffff; }
        for (int c = 0; c < 96; c++) {
            float v = vals[c]; int j = cols[c];
            if (v > tv[9] || (v == tv[9] && j < tix[9])) insert10(tv, tix, v, j);
        }
        float mx = tv[0];
        float e[10], sum = 0.0f;
#pragma unroll
        for (int q = 0; q < 10; q++) { e[q] = expf((tv[q] - mx) * INV_TAU); sum += e[q]; }
        float inv = 1.0f / sum;
#pragma unroll
        for (int q = 0; q < 10; q++) {
            out[m * 10 + q]           = e[q] * inv;
            out[NXK + m * 10 + q]     = (float)m;
            out[2 * NXK + m * 10 + q] = (float)tix[q];
        }
    }
}

// ---------------- launch ----------------
extern "C" void kernel_launch(void* const* d_in, const int* in_sizes, int n_in,
                              void* d_out, int out_size) {
    const float* fx = (const float*)d_in[0];
    const float* fy = (const float*)d_in[1];
    if (n_in >= 2 && in_sizes[0] == NYC * CDIM && in_sizes[1] == NXC * CDIM) {
        const float* t = fx; fx = fy; fy = t;
    }
    float* outF = (float*)d_out;

    cudaFuncSetAttribute(gemm_topk_kernel,
                         cudaFuncAttributeMaxDynamicSharedMemorySize, SM_TOTAL);
    cudaFuncSetAttribute(rescore_kernel,
                         cudaFuncAttributeMaxDynamicSharedMemorySize, 50816);

    norm_x_kernel<<<NXC / 8, 256>>>(fx);                                  // launch 1
    norm_y_kernel<<<NY_PAD / 8, 256>>>(fy);                               // launch 2
    pack_xy_frag<<<(NPACK_X + NPACK_Y + 255) / 256, 256>>>();             // launch 3
    gemm_topk_kernel<<<dim3(MTILES, 2), 128, SM_TOTAL>>>();               // launch 4 (ncu target)
    rescore_kernel<<<NXC, 128, 50816>>>(outF);                            // launch 5
}

// round 14
// speedup vs baseline: 1.6485x; 1.6485x over previous
#include <cuda_runtime.h>
#include <cuda_bf16.h>
#include <cstdint>
#include <math.h>

#define NXC 49152
#define NYC 50000
#define NT_Y64 782                 // 64-col y tiles
#define NY_PAD (NT_Y64*64)         // 50048
#define CDIM 128
#define KTOP 10
#define DEPTH 12
#define NCAND 96                   // 2 splits * 4 class-threads * 12
#define NXK (NXC*KTOP)
#define INV_TAU 20.0f

#define MTILES (NXC/64)            // 768
#define SPLIT_T 391                // split0: [0,391), split1: [391,782)

// gemm smem: A 32KB @0, B0 32KB @32768, B1 32KB @65536
#define SM_B0 32768
#define SM_B1 65536
#define SM_TOTAL 98304

#define NPACK_X (MTILES*2048)      // A-image uint4 count
#define NPACK_Y (NT_Y64*2048)      // B-image uint4 count

// ---------------- device scratch ----------------
__device__ float g_x32[NXC*CDIM];      // normalized x, row-major (exact fp32)
__device__ float g_y32[NY_PAD*CDIM];   // normalized y, row-major, zero-padded
__device__ uint4 g_xA[NPACK_X];        // tf32 A fragment images: 32KB per 64-row tile
__device__ uint4 g_yB[NPACK_Y];        // tf32 B fragment images: 32KB per 64-col tile
__device__ int   g_candI[NXC*NCAND];   // candidate cols per row

// ---------------- helpers ----------------
__device__ __forceinline__ unsigned tf32_of(float f) {
    unsigned u; asm("cvt.rna.tf32.f32 %0, %1;" : "=r"(u) : "f"(f)); return u;
}
__device__ __forceinline__ void mma_tf32(float (&c)[4], const uint4& a, unsigned b0, unsigned b1) {
    asm volatile(
        "mma.sync.aligned.m16n8k8.row.col.f32.tf32.tf32.f32 "
        "{%0,%1,%2,%3}, {%4,%5,%6,%7}, {%8,%9}, {%0,%1,%2,%3};"
        : "+f"(c[0]), "+f"(c[1]), "+f"(c[2]), "+f"(c[3])
        : "r"(a.x), "r"(a.y), "r"(a.z), "r"(a.w), "r"(b0), "r"(b1));
}
__device__ __forceinline__ void insert12(float (&tv)[12], int (&ti)[12], float v, int j) {
    tv[11] = v; ti[11] = j;
#pragma unroll
    for (int s = 11; s > 0; --s) {
        bool sw = (tv[s] > tv[s-1]) || (tv[s] == tv[s-1] && ti[s] < ti[s-1]);
        if (sw) {
            float fv = tv[s]; tv[s] = tv[s-1]; tv[s-1] = fv;
            int   fi = ti[s]; ti[s] = ti[s-1]; ti[s-1] = fi;
        }
    }
}
__device__ __forceinline__ void insert10(float (&tv)[10], int (&ti)[10], float v, int j) {
    tv[9] = v; ti[9] = j;
#pragma unroll
    for (int s = 9; s > 0; --s) {
        bool sw = (tv[s] > tv[s-1]) || (tv[s] == tv[s-1] && ti[s] < ti[s-1]);
        if (sw) {
            float fv = tv[s]; tv[s] = tv[s-1]; tv[s-1] = fv;
            int   fi = ti[s]; ti[s] = ti[s-1]; ti[s-1] = fi;
        }
    }
}

// ---------------- normalize (EXACT same arithmetic as the passing chain) ----------------
__global__ void norm_x_kernel(const float* __restrict__ in) {
    int warp = (blockIdx.x * blockDim.x + threadIdx.x) >> 5;
    int lane = threadIdx.x & 31;
    if (warp >= NXC) return;
    float4 v = *(const float4*)&in[warp * CDIM + lane * 4];
    float ss = v.x*v.x + v.y*v.y + v.z*v.z + v.w*v.w;
#pragma unroll
    for (int o = 16; o > 0; o >>= 1) ss += __shfl_xor_sync(0xffffffffu, ss, o);
    float inv = 1.0f / fmaxf(sqrtf(ss), 1e-12f);
    *(float4*)&g_x32[warp * CDIM + lane * 4] = make_float4(v.x*inv, v.y*inv, v.z*inv, v.w*inv);
}
__global__ void norm_y_kernel(const float* __restrict__ in) {
    int warp = (blockIdx.x * blockDim.x + threadIdx.x) >> 5;
    int lane = threadIdx.x & 31;
    if (warp >= NY_PAD) return;
    if (warp >= NYC) {
        *(float4*)&g_y32[warp * CDIM + lane * 4] = make_float4(0.f, 0.f, 0.f, 0.f);
        return;
    }
    float4 v = *(const float4*)&in[warp * CDIM + lane * 4];
    float ss = v.x*v.x + v.y*v.y + v.z*v.z + v.w*v.w;
#pragma unroll
    for (int o = 16; o > 0; o >>= 1) ss += __shfl_xor_sync(0xffffffffu, ss, o);
    float inv = 1.0f / fmaxf(sqrtf(ss), 1e-12f);
    *(float4*)&g_y32[warp * CDIM + lane * 4] = make_float4(v.x*inv, v.y*inv, v.z*inv, v.w*inv);
}

// ---------------- fused tf32 fragment packing (single launch -> gemm is launch #4) ----
// A image per 64-row mtile: uint4 i = mt*2048 + (w*16 + k8)*32 + lane
//   lane=i&31, k8=(i>>5)&15, w=(i>>9)&3, mt=i>>11
//   g=lane>>2, t=lane&3; r=mt*64+w*16+g; k=k8*8+t
//   a = { A[r][k], A[r+8][k], A[r][k+4], A[r+8][k+4] }
// B image per 64-col ytile: uint4 j = yt*2048 + (k8*4 + p)*32 + lane
//   lane=j&31, p=(j>>5)&3, k8=(j>>7)&15, yt=j>>11
//   n_e=yt*64+p*16+g; n_o=n_e+8; k=k8*8+t
//   b = { B[n_e][k], B[n_e][k+4], B[n_o][k], B[n_o][k+4] }
__global__ void pack_xy_frag() {
    int i = blockIdx.x * blockDim.x + threadIdx.x;
    if (i < NPACK_X) {
        int lane = i & 31;
        int k8   = (i >> 5) & 15;
        int w    = (i >> 9) & 3;
        int mt   = i >> 11;
        int g = lane >> 2, t = lane & 3;
        int r = mt * 64 + w * 16 + g;
        int k = k8 * 8 + t;
        uint4 a;
        a.x = tf32_of(g_x32[r * CDIM + k]);
        a.y = tf32_of(g_x32[(r + 8) * CDIM + k]);
        a.z = tf32_of(g_x32[r * CDIM + k + 4]);
        a.w = tf32_of(g_x32[(r + 8) * CDIM + k + 4]);
        g_xA[i] = a;
        return;
    }
    int j = i - NPACK_X;
    if (j >= NPACK_Y) return;
    int lane = j & 31;
    int p    = (j >> 5) & 3;
    int k8   = (j >> 7) & 15;
    int yt   = j >> 11;
    int g = lane >> 2, t = lane & 3;
    int ce = yt * 64 + p * 16 + g;
    int co = ce + 8;
    int k = k8 * 8 + t;
    uint4 b;
    b.x = tf32_of(g_y32[ce * CDIM + k]);
    b.y = tf32_of(g_y32[ce * CDIM + k + 4]);
    b.z = tf32_of(g_y32[co * CDIM + k]);
    b.w = tf32_of(g_y32[co * CDIM + k + 4]);
    g_yB[j] = b;
}

// ---------------- 32KB cp.async (128 threads, 16x 2KB rounds) ----------------
__device__ __forceinline__ void cp32k(char* dst_sm, const char* src, int tid) {
#pragma unroll
    for (int i = 0; i < 16; i++) {
        int off = (tid + 128 * i) * 16;
        unsigned s = (unsigned)__cvta_generic_to_shared(dst_sm + off);
        asm volatile("cp.async.cg.shared.global [%0], [%1], 16;" :: "r"(s), "l"(src + off));
    }
    asm volatile("cp.async.commit_group;" ::: "memory");
}

// ---------------- tf32 mma GEMM + in-register streaming top-12 ----------------
__global__ __launch_bounds__(128, 2) void gemm_topk_kernel() {
    extern __shared__ char sm[];
    const int tid  = threadIdx.x;
    const int w    = tid >> 5;
    const int lane = tid & 31;
    const int g    = lane >> 2;
    const int t4   = lane & 3;
    const int mtile = blockIdx.x;
    const int split = blockIdx.y;
    const int t_lo = split * SPLIT_T;
    const int t_hi = split ? NT_Y64 : SPLIT_T;

    cp32k(sm, (const char*)(g_xA + (size_t)mtile * 2048), tid);
    cp32k(sm + SM_B0, (const char*)(g_yB + (size_t)t_lo * 2048), tid);   // rel tile 0 -> buf 0

    const uint4* AsW = (const uint4*)sm + w * 16 * 32;   // this warp's m-frag, 16 k8 slabs

    float tvA[12], tvB[12]; int tiA[12], tiB[12];
#pragma unroll
    for (int q = 0; q < 12; q++) {
        tvA[q] = tvB[q] = -__int_as_float(0x7f800000);
        tiA[q] = tiB[q] = 0x7fffffff;
    }

    for (int t = t_lo; t < t_hi; t++) {
        const int rel = t - t_lo;                         // PARITY FIX: buffer index is
        if (t + 1 < t_hi) {                               // relative to t_lo, not absolute
            cp32k(sm + (((rel + 1) & 1) ? SM_B1 : SM_B0),
                  (const char*)(g_yB + (size_t)(t + 1) * 2048), tid);
            asm volatile("cp.async.wait_group 1;" ::: "memory");
        } else {
            asm volatile("cp.async.wait_group 0;" ::: "memory");
        }
        __syncthreads();

        const uint4* Bs = (const uint4*)(sm + ((rel & 1) ? SM_B1 : SM_B0));

        float acc[8][4];
#pragma unroll
        for (int nf = 0; nf < 8; nf++)
#pragma unroll
            for (int p = 0; p < 4; p++) acc[nf][p] = 0.0f;

#pragma unroll
        for (int k8 = 0; k8 < 16; k8++) {
            uint4 a = AsW[k8 * 32 + lane];
            const uint4* Bk = Bs + k8 * 4 * 32;
#pragma unroll
            for (int p = 0; p < 4; p++) {
                uint4 bb = Bk[p * 32 + lane];
                mma_tf32(acc[2*p],     a, bb.x, bb.y);
                mma_tf32(acc[2*p + 1], a, bb.z, bb.w);
            }
        }

        // scan: thread owns rows (g, g+8); cols nf*8 + t4*2 + {0,1}
        int n0 = t * 64 + t4 * 2;
#pragma unroll
        for (int nf = 0; nf < 8; nf++) {
            int j0 = n0 + nf * 8;
            float v0 = acc[nf][0], v1 = acc[nf][1], v2 = acc[nf][2], v3 = acc[nf][3];
            if (v0 > tvA[11] && j0 < NYC)     insert12(tvA, tiA, v0, j0);
            if (v1 > tvA[11] && j0 + 1 < NYC) insert12(tvA, tiA, v1, j0 + 1);
            if (v2 > tvB[11] && j0 < NYC)     insert12(tvB, tiB, v2, j0);
            if (v3 > tvB[11] && j0 + 1 < NYC) insert12(tvB, tiB, v3, j0 + 1);
        }
        __syncthreads();   // all warps done with this B buffer before next-iter cp overwrites it
    }

    int mA = mtile * 64 + w * 16 + g;
    int mB = mA + 8;
    int base = split * 48 + t4 * 12;
#pragma unroll
    for (int q = 0; q < 12; q++) {
        g_candI[mA * NCAND + base + q] = tiA[q];
        g_candI[mB * NCAND + base + q] = tiB[q];
    }
}

// ---------------- exact fp32 rescore (bitwise-identical chain) + softmax + COO ----------------
__global__ __launch_bounds__(128) void rescore_kernel(float* __restrict__ out) {
    extern __shared__ float rs[];
    float* xrow  = rs;                        // 128
    float* yrows = rs + 128;                  // 96 * 129 (pitch 129 -> conflict-free)
    float* vals  = yrows + 96 * 129;          // 96
    int*   cols  = (int*)(vals + 96);         // 96

    const int m = blockIdx.x;
    const int tid = threadIdx.x;

    if (tid < 128) xrow[tid] = g_x32[m * CDIM + tid];
    if (tid < 96)  cols[tid] = g_candI[m * NCAND + tid];
    __syncthreads();

    for (int i = tid; i < 96 * 32; i += 128) {
        int c = i >> 5, p = i & 31;
        float4 v = *(const float4*)&g_y32[(size_t)cols[c] * CDIM + p * 4];
        float* dst = &yrows[c * 129 + p * 4];
        dst[0] = v.x; dst[1] = v.y; dst[2] = v.z; dst[3] = v.w;
    }
    __syncthreads();

    if (tid < 96) {
        float s = 0.0f;
        const float* yr = &yrows[tid * 129];
#pragma unroll 16
        for (int k = 0; k < 128; k++) s = fmaf(xrow[k], yr[k], s);
        vals[tid] = s;
    }
    __syncthreads();

    if (tid == 0) {
        float tv[10]; int tix[10];
#pragma unroll
        for (int q = 0; q < 10; q++) { tv[q] = -__int_as_float(0x7f800000); tix[q] = 0x7fffffff; }
        for (int c = 0; c < 96; c++) {
            float v = vals[c]; int j = cols[c];
            if (v > tv[9] || (v == tv[9] && j < tix[9])) insert10(tv, tix, v, j);
        }
        float mx = tv[0];
        float e[10], sum = 0.0f;
#pragma unroll
        for (int q = 0; q < 10; q++) { e[q] = expf((tv[q] - mx) * INV_TAU); sum += e[q]; }
        float inv = 1.0f / sum;
#pragma unroll
        for (int q = 0; q < 10; q++) {
            out[m * 10 + q]           = e[q] * inv;
            out[NXK + m * 10 + q]     = (float)m;
            out[2 * NXK + m * 10 + q] = (float)tix[q];
        }
    }
}

// ---------------- launch ----------------
extern "C" void kernel_launch(void* const* d_in, const int* in_sizes, int n_in,
                              void* d_out, int out_size) {
    const float* fx = (const float*)d_in[0];
    const float* fy = (const float*)d_in[1];
    if (n_in >= 2 && in_sizes[0] == NYC * CDIM && in_sizes[1] == NXC * CDIM) {
        const float* t = fx; fx = fy; fy = t;
    }
    float* outF = (float*)d_out;

    cudaFuncSetAttribute(gemm_topk_kernel,
                         cudaFuncAttributeMaxDynamicSharedMemorySize, SM_TOTAL);
    cudaFuncSetAttribute(rescore_kernel,
                         cudaFuncAttributeMaxDynamicSharedMemorySize, 50816);

    norm_x_kernel<<<NXC / 8, 256>>>(fx);                                  // launch 1
    norm_y_kernel<<<NY_PAD / 8, 256>>>(fy);                               // launch 2
    pack_xy_frag<<<(NPACK_X + NPACK_Y + 255) / 256, 256>>>();             // launch 3
    gemm_topk_kernel<<<dim3(MTILES, 2), 128, SM_TOTAL>>>();               // launch 4 (ncu target)
    rescore_kernel<<<NXC, 128, 50816>>>(outF);                            // launch 5
}